// round 11
// baseline (speedup 1.0000x reference)
#include <cuda_runtime.h>
#include <cuda_bf16.h>

// Problem shape (fixed by reference setup_inputs)
#define B_DIM 32
#define C_DIM 512
#define HW    4096            // 64*64
#define KTOP  256             // 0.5 * C
#define NBC   (B_DIM * C_DIM) // 16384
#define SEL_BLOCKS 128        // 32 batches x 4 channel groups

// Fixed-point encoding for the single-atomic final reduction.
// Block partial <= ~1.3e6 (ssd ~8192 x 128 channels); x 2^18 ~= 3.4e11 << 2^57.
// Sum of 128 partials ~= 4.4e13 << 2^57. Count lives in bits [57,64).
#define FIXED_SCALE 262144.0f            // 2^18
#define COUNT_INC   (1ULL << 57)
#define SUM_MASK    (COUNT_INC - 1ULL)

// Scratch (no cudaMalloc allowed; zero-initialized at module load)
__device__ float g_ssq[NBC];            // per-(b,c) sum of targets^2 (ranking key)
__device__ float g_ssd[NBC];            // per-(b,c) sum of (in - tgt)^2
__device__ unsigned long long g_acc;    // packed {count:7, fixed-point sum:57}; self-reset

// ---------------------------------------------------------------------------
// Kernel 1: streaming reduce (UNCHANGED from the 82.7us config — at the HBM
// wall; exit path stays pure per the R4/R6/R8 n=3 lesson). 512 threads per
// block, two (b,c) planes per block, 8x LDG.128 streaming per thread.
// ---------------------------------------------------------------------------
__global__ __launch_bounds__(512, 4) void bc_reduce_kernel(
    const float* __restrict__ inp,
    const float* __restrict__ tgt)
{
    const int bid = blockIdx.x;                 // 0 .. NBC/2-1
    const int t   = threadIdx.x;                // 0 .. 511
    const int half = t >> 8;                    // which plane
    const int t256 = t & 255;

    const size_t plane = (size_t)(2 * bid + half);
    const float4* __restrict__ ip =
        reinterpret_cast<const float4*>(inp + plane * HW);
    const float4* __restrict__ tp =
        reinterpret_cast<const float4*>(tgt + plane * HW);

    float ssq = 0.0f;
    float ssd = 0.0f;

#pragma unroll
    for (int i = 0; i < 4; i++) {
        float4 a = __ldcs(ip + t256 + i * 256);
        float4 b = __ldcs(tp + t256 + i * 256);
        ssq = fmaf(b.x, b.x, ssq);
        ssq = fmaf(b.y, b.y, ssq);
        ssq = fmaf(b.z, b.z, ssq);
        ssq = fmaf(b.w, b.w, ssq);
        float dx = a.x - b.x;
        float dy = a.y - b.y;
        float dz = a.z - b.z;
        float dw = a.w - b.w;
        ssd = fmaf(dx, dx, ssd);
        ssd = fmaf(dy, dy, ssd);
        ssd = fmaf(dz, dz, ssd);
        ssd = fmaf(dw, dw, ssd);
    }

#pragma unroll
    for (int off = 16; off > 0; off >>= 1) {
        ssq += __shfl_xor_sync(0xFFFFFFFFu, ssq, off);
        ssd += __shfl_xor_sync(0xFFFFFFFFu, ssd, off);
    }

    __shared__ float s_ssq[16];
    __shared__ float s_ssd[16];
    const int warp = t >> 5;                    // 0..15 (0-7 plane0, 8-15 plane1)
    const int lane = t & 31;
    if (lane == 0) {
        s_ssq[warp] = ssq;
        s_ssd[warp] = ssd;
    }
    __syncthreads();

    if (warp == 0) {
        float q = (lane < 16) ? s_ssq[lane] : 0.0f;
        float d = (lane < 16) ? s_ssd[lane] : 0.0f;
#pragma unroll
        for (int off = 4; off > 0; off >>= 1) {   // xor 4,2,1 stays within each 8-group
            q += __shfl_xor_sync(0xFFFFFFFFu, q, off);
            d += __shfl_xor_sync(0xFFFFFFFFu, d, off);
        }
        if (lane == 0) {
            g_ssq[2 * bid] = q;
            g_ssd[2 * bid] = d;
        }
        if (lane == 8) {
            g_ssq[2 * bid + 1] = q;
            g_ssd[2 * bid + 1] = d;
        }
    }

    __syncthreads();
    cudaTriggerProgrammaticLaunchCompletion();
}

// ---------------------------------------------------------------------------
// Kernel 2: select + final (PDL secondary). 128 blocks x 256 threads.
// Each block: one (batch, 128-channel group). The 512-way rank count per
// channel is SPLIT across two threads (64 float4 iters each), combined via
// SMEM. Block partial is converted to fixed-point and folded into ONE packed
// u64 atomicAdd (sum in low 57 bits, arrival count in top 7). The 128th
// arrival computes the exact integer total, writes the scalar, resets g_acc.
// Integer adds commute -> bitwise deterministic for any arrival order.
// ---------------------------------------------------------------------------
__global__ __launch_bounds__(256) void select_final_kernel(float* __restrict__ out)
{
    // PDL: wait until the upstream grid's memory (g_ssq/g_ssd) is visible.
    cudaGridDependencySynchronize();

    __shared__ float4 s_norm4[C_DIM / 4];   // all 512 norms of this batch
    __shared__ int    s_cnt[128];           // half-1 partial counts
    __shared__ float  s_p[8];

    const int b  = blockIdx.x >> 2;    // batch
    const int g  = blockIdx.x & 3;     // channel group (128 channels)
    const int t  = threadIdx.x;        // 0..255
    const int cl = t & 127;            // channel-within-group
    const int hf = t >> 7;             // which half of the 512 to scan
    const int warp = t >> 5;
    const int lane = t & 31;
    const int c = g * 128 + cl;        // this thread's channel

    // Hoist global loads: latency hides under the rank loop.
    const float my_ssd = (hf == 0) ? g_ssd[b * C_DIM + c] : 0.0f;
    if (t < C_DIM / 4)
        s_norm4[t] = reinterpret_cast<const float4*>(g_ssq + b * C_DIM)[t];
    __syncthreads();

    const float v = reinterpret_cast<const float*>(s_norm4)[c];

    // Each thread scans 64 float4 (256 norms): half 0 -> j in [0,64),
    // half 1 -> j in [64,128).
    int cnt = 0;
    const int j0 = hf * 64;
#pragma unroll 4
    for (int j = j0; j < j0 + 64; j++) {
        float4 n = s_norm4[j];         // broadcast, conflict-free
        cnt += (n.x > v) ? 1 : 0;
        cnt += (n.y > v) ? 1 : 0;
        cnt += (n.z > v) ? 1 : 0;
        cnt += (n.w > v) ? 1 : 0;
    }

    if (hf == 1) s_cnt[cl] = cnt;
    __syncthreads();

    float contrib = 0.0f;
    if (hf == 0) {
        const int total_cnt = cnt + s_cnt[cl];
        contrib = (total_cnt < KTOP) ? my_ssd : 0.0f;
    }

#pragma unroll
    for (int off = 16; off > 0; off >>= 1)
        contrib += __shfl_xor_sync(0xFFFFFFFFu, contrib, off);
    if (lane == 0) s_p[warp] = contrib;
    __syncthreads();

    if (t == 0) {
        const float part = ((s_p[0] + s_p[1]) + (s_p[2] + s_p[3]))
                         + ((s_p[4] + s_p[5]) + (s_p[6] + s_p[7]));
        // Fixed-point fold + arrival count, in ONE relaxed atomic.
        const unsigned long long mine =
            (unsigned long long)(part * FIXED_SCALE) + COUNT_INC;
        const unsigned long long prev = atomicAdd(&g_acc, mine);
        if ((prev >> 57) == (unsigned long long)(SEL_BLOCKS - 1)) {
            // I'm the 128th arrival: exact integer total is prev's sum + mine.
            const unsigned long long tot = (prev & SUM_MASK) + (mine & SUM_MASK);
            out[0] = ((float)tot / FIXED_SCALE)
                   / ((float)HW * (float)(B_DIM * KTOP));
            g_acc = 0ULL;              // reset for next graph replay
        }
    }
}

extern "C" void kernel_launch(void* const* d_in, const int* in_sizes, int n_in,
                              void* d_out, int out_size)
{
    const float* inputs  = (const float*)d_in[0];
    const float* targets = (const float*)d_in[1];
    float* out = (float*)d_out;

    bc_reduce_kernel<<<NBC / 2, 512>>>(inputs, targets);

    // Dependent launch with programmatic stream serialization (PDL):
    // select_final_kernel's launch/prologue overlaps bc_reduce's tail.
    cudaLaunchConfig_t cfg = {};
    cfg.gridDim  = dim3(SEL_BLOCKS);
    cfg.blockDim = dim3(256);
    cfg.dynamicSmemBytes = 0;
    cfg.stream = 0;   // legacy default stream (same as <<<>>> above)
    cudaLaunchAttribute attrs[1];
    attrs[0].id = cudaLaunchAttributeProgrammaticStreamSerialization;
    attrs[0].val.programmaticStreamSerializationAllowed = 1;
    cfg.attrs = attrs;
    cfg.numAttrs = 1;
    cudaLaunchKernelEx(&cfg, select_final_kernel, out);
}

// round 12
// speedup vs baseline: 1.0032x; 1.0032x over previous
#include <cuda_runtime.h>
#include <cuda_bf16.h>

// Problem shape (fixed by reference setup_inputs)
#define B_DIM 32
#define C_DIM 512
#define HW    4096            // 64*64
#define KTOP  256             // 0.5 * C
#define NBC   (B_DIM * C_DIM) // 16384
#define SEL_BLOCKS 128        // 32 batches x 4 channel groups

// Fixed-point encoding for the single-atomic final reduction.
// Block partial <= ~1.3e6 (ssd ~8192 x 128 channels); x 2^18 ~= 3.4e11 << 2^57.
// Sum of 128 partials ~= 4.4e13 << 2^57. Count lives in bits [57,64).
#define FIXED_SCALE 262144.0f            // 2^18
#define COUNT_INC   (1ULL << 57)
#define SUM_MASK    (COUNT_INC - 1ULL)

// Scratch (no cudaMalloc allowed; zero-initialized at module load)
__device__ float g_ssq[NBC];            // per-(b,c) sum of targets^2 (ranking key)
__device__ float g_ssd[NBC];            // per-(b,c) sum of (in - tgt)^2
__device__ unsigned long long g_acc;    // packed {count:7, fixed-point sum:57}; self-reset

// ---------------------------------------------------------------------------
// Kernel 1: streaming reduce (UNCHANGED from the 82.7us config — at the HBM
// wall; exit path stays pure per the R4/R6/R8 n=3 lesson). 512 threads per
// block, two (b,c) planes per block, 8x LDG.128 streaming per thread.
// ---------------------------------------------------------------------------
__global__ __launch_bounds__(512, 4) void bc_reduce_kernel(
    const float* __restrict__ inp,
    const float* __restrict__ tgt)
{
    const int bid = blockIdx.x;                 // 0 .. NBC/2-1
    const int t   = threadIdx.x;                // 0 .. 511
    const int half = t >> 8;                    // which plane
    const int t256 = t & 255;

    const size_t plane = (size_t)(2 * bid + half);
    const float4* __restrict__ ip =
        reinterpret_cast<const float4*>(inp + plane * HW);
    const float4* __restrict__ tp =
        reinterpret_cast<const float4*>(tgt + plane * HW);

    float ssq = 0.0f;
    float ssd = 0.0f;

#pragma unroll
    for (int i = 0; i < 4; i++) {
        float4 a = __ldcs(ip + t256 + i * 256);
        float4 b = __ldcs(tp + t256 + i * 256);
        ssq = fmaf(b.x, b.x, ssq);
        ssq = fmaf(b.y, b.y, ssq);
        ssq = fmaf(b.z, b.z, ssq);
        ssq = fmaf(b.w, b.w, ssq);
        float dx = a.x - b.x;
        float dy = a.y - b.y;
        float dz = a.z - b.z;
        float dw = a.w - b.w;
        ssd = fmaf(dx, dx, ssd);
        ssd = fmaf(dy, dy, ssd);
        ssd = fmaf(dz, dz, ssd);
        ssd = fmaf(dw, dw, ssd);
    }

#pragma unroll
    for (int off = 16; off > 0; off >>= 1) {
        ssq += __shfl_xor_sync(0xFFFFFFFFu, ssq, off);
        ssd += __shfl_xor_sync(0xFFFFFFFFu, ssd, off);
    }

    __shared__ float s_ssq[16];
    __shared__ float s_ssd[16];
    const int warp = t >> 5;                    // 0..15 (0-7 plane0, 8-15 plane1)
    const int lane = t & 31;
    if (lane == 0) {
        s_ssq[warp] = ssq;
        s_ssd[warp] = ssd;
    }
    __syncthreads();

    if (warp == 0) {
        float q = (lane < 16) ? s_ssq[lane] : 0.0f;
        float d = (lane < 16) ? s_ssd[lane] : 0.0f;
#pragma unroll
        for (int off = 4; off > 0; off >>= 1) {   // xor 4,2,1 stays within each 8-group
            q += __shfl_xor_sync(0xFFFFFFFFu, q, off);
            d += __shfl_xor_sync(0xFFFFFFFFu, d, off);
        }
        if (lane == 0) {
            g_ssq[2 * bid] = q;
            g_ssd[2 * bid] = d;
        }
        if (lane == 8) {
            g_ssq[2 * bid + 1] = q;
            g_ssd[2 * bid + 1] = d;
        }
    }

    __syncthreads();
    cudaTriggerProgrammaticLaunchCompletion();
}

// ---------------------------------------------------------------------------
// Kernel 2: select + final (PDL secondary). 128 blocks x 256 threads.
// Each block: one (batch, 128-channel group). The 512-way rank count per
// channel is SPLIT across two threads (64 float4 iters each), combined via
// SMEM. Block partial is converted to fixed-point and folded into ONE packed
// u64 atomicAdd (sum in low 57 bits, arrival count in top 7). The 128th
// arrival computes the exact integer total, writes the scalar, resets g_acc.
// Integer adds commute -> bitwise deterministic for any arrival order.
// ---------------------------------------------------------------------------
__global__ __launch_bounds__(256) void select_final_kernel(float* __restrict__ out)
{
    // PDL: wait until the upstream grid's memory (g_ssq/g_ssd) is visible.
    cudaGridDependencySynchronize();

    __shared__ float4 s_norm4[C_DIM / 4];   // all 512 norms of this batch
    __shared__ int    s_cnt[128];           // half-1 partial counts
    __shared__ float  s_p[8];

    const int b  = blockIdx.x >> 2;    // batch
    const int g  = blockIdx.x & 3;     // channel group (128 channels)
    const int t  = threadIdx.x;        // 0..255
    const int cl = t & 127;            // channel-within-group
    const int hf = t >> 7;             // which half of the 512 to scan
    const int warp = t >> 5;
    const int lane = t & 31;
    const int c = g * 128 + cl;        // this thread's channel

    // Hoist global loads: latency hides under the rank loop.
    const float my_ssd = (hf == 0) ? g_ssd[b * C_DIM + c] : 0.0f;
    if (t < C_DIM / 4)
        s_norm4[t] = reinterpret_cast<const float4*>(g_ssq + b * C_DIM)[t];
    __syncthreads();

    const float v = reinterpret_cast<const float*>(s_norm4)[c];

    // Each thread scans 64 float4 (256 norms): half 0 -> j in [0,64),
    // half 1 -> j in [64,128).
    int cnt = 0;
    const int j0 = hf * 64;
#pragma unroll 4
    for (int j = j0; j < j0 + 64; j++) {
        float4 n = s_norm4[j];         // broadcast, conflict-free
        cnt += (n.x > v) ? 1 : 0;
        cnt += (n.y > v) ? 1 : 0;
        cnt += (n.z > v) ? 1 : 0;
        cnt += (n.w > v) ? 1 : 0;
    }

    if (hf == 1) s_cnt[cl] = cnt;
    __syncthreads();

    float contrib = 0.0f;
    if (hf == 0) {
        const int total_cnt = cnt + s_cnt[cl];
        contrib = (total_cnt < KTOP) ? my_ssd : 0.0f;
    }

#pragma unroll
    for (int off = 16; off > 0; off >>= 1)
        contrib += __shfl_xor_sync(0xFFFFFFFFu, contrib, off);
    if (lane == 0) s_p[warp] = contrib;
    __syncthreads();

    if (t == 0) {
        const float part = ((s_p[0] + s_p[1]) + (s_p[2] + s_p[3]))
                         + ((s_p[4] + s_p[5]) + (s_p[6] + s_p[7]));
        // Fixed-point fold + arrival count, in ONE relaxed atomic.
        const unsigned long long mine =
            (unsigned long long)(part * FIXED_SCALE) + COUNT_INC;
        const unsigned long long prev = atomicAdd(&g_acc, mine);
        if ((prev >> 57) == (unsigned long long)(SEL_BLOCKS - 1)) {
            // I'm the 128th arrival: exact integer total is prev's sum + mine.
            const unsigned long long tot = (prev & SUM_MASK) + (mine & SUM_MASK);
            out[0] = ((float)tot / FIXED_SCALE)
                   / ((float)HW * (float)(B_DIM * KTOP));
            g_acc = 0ULL;              // reset for next graph replay
        }
    }
}

extern "C" void kernel_launch(void* const* d_in, const int* in_sizes, int n_in,
                              void* d_out, int out_size)
{
    const float* inputs  = (const float*)d_in[0];
    const float* targets = (const float*)d_in[1];
    float* out = (float*)d_out;

    bc_reduce_kernel<<<NBC / 2, 512>>>(inputs, targets);

    // Dependent launch with programmatic stream serialization (PDL):
    // select_final_kernel's launch/prologue overlaps bc_reduce's tail.
    cudaLaunchConfig_t cfg = {};
    cfg.gridDim  = dim3(SEL_BLOCKS);
    cfg.blockDim = dim3(256);
    cfg.dynamicSmemBytes = 0;
    cfg.stream = 0;   // legacy default stream (same as <<<>>> above)
    cudaLaunchAttribute attrs[1];
    attrs[0].id = cudaLaunchAttributeProgrammaticStreamSerialization;
    attrs[0].val.programmaticStreamSerializationAllowed = 1;
    cfg.attrs = attrs;
    cfg.numAttrs = 1;
    cudaLaunchKernelEx(&cfg, select_final_kernel, out);
}

// round 13
// speedup vs baseline: 1.0064x; 1.0032x over previous
#include <cuda_runtime.h>
#include <cuda_bf16.h>

// Problem shape (fixed by reference setup_inputs)
#define B_DIM 32
#define C_DIM 512
#define HW    4096            // 64*64
#define KTOP  256             // 0.5 * C
#define NBC   (B_DIM * C_DIM) // 16384
#define SEL_BLOCKS 128        // 32 batches x 4 channel groups

// Fixed-point encoding for the single-atomic final reduction.
// Block partial <= ~1.3e6; x 2^18 ~= 3.4e11; x128 blocks ~= 4.4e13 << 2^57.
// Arrival count lives in bits [57,64).
#define FIXED_SCALE 262144.0f            // 2^18
#define COUNT_INC   (1ULL << 57)
#define SUM_MASK    (COUNT_INC - 1ULL)

// Scratch (no cudaMalloc allowed; zero-initialized at module load)
__device__ float g_ssq[NBC];            // per-(b,c) sum of targets^2 (ranking key)
__device__ float g_ssd[NBC];            // per-(b,c) sum of (in - tgt)^2
__device__ unsigned long long g_acc;    // packed {count:7, fixed sum:57}; self-reset

// ---------------------------------------------------------------------------
// Kernel 1: streaming reduce (UNCHANGED — ~98% of the path-independent LTS
// throughput cap; exit path stays pure per the R4/R6/R8 n=3 lesson).
// 512 threads per block, two (b,c) planes per block, 8x LDG.128 streaming.
// ---------------------------------------------------------------------------
__global__ __launch_bounds__(512, 4) void bc_reduce_kernel(
    const float* __restrict__ inp,
    const float* __restrict__ tgt)
{
    const int bid = blockIdx.x;                 // 0 .. NBC/2-1
    const int t   = threadIdx.x;                // 0 .. 511
    const int half = t >> 8;                    // which plane
    const int t256 = t & 255;

    const size_t plane = (size_t)(2 * bid + half);
    const float4* __restrict__ ip =
        reinterpret_cast<const float4*>(inp + plane * HW);
    const float4* __restrict__ tp =
        reinterpret_cast<const float4*>(tgt + plane * HW);

    float ssq = 0.0f;
    float ssd = 0.0f;

#pragma unroll
    for (int i = 0; i < 4; i++) {
        float4 a = __ldcs(ip + t256 + i * 256);
        float4 b = __ldcs(tp + t256 + i * 256);
        ssq = fmaf(b.x, b.x, ssq);
        ssq = fmaf(b.y, b.y, ssq);
        ssq = fmaf(b.z, b.z, ssq);
        ssq = fmaf(b.w, b.w, ssq);
        float dx = a.x - b.x;
        float dy = a.y - b.y;
        float dz = a.z - b.z;
        float dw = a.w - b.w;
        ssd = fmaf(dx, dx, ssd);
        ssd = fmaf(dy, dy, ssd);
        ssd = fmaf(dz, dz, ssd);
        ssd = fmaf(dw, dw, ssd);
    }

#pragma unroll
    for (int off = 16; off > 0; off >>= 1) {
        ssq += __shfl_xor_sync(0xFFFFFFFFu, ssq, off);
        ssd += __shfl_xor_sync(0xFFFFFFFFu, ssd, off);
    }

    __shared__ float s_ssq[16];
    __shared__ float s_ssd[16];
    const int warp = t >> 5;                    // 0..15 (0-7 plane0, 8-15 plane1)
    const int lane = t & 31;
    if (lane == 0) {
        s_ssq[warp] = ssq;
        s_ssd[warp] = ssd;
    }
    __syncthreads();

    if (warp == 0) {
        float q = (lane < 16) ? s_ssq[lane] : 0.0f;
        float d = (lane < 16) ? s_ssd[lane] : 0.0f;
#pragma unroll
        for (int off = 4; off > 0; off >>= 1) {   // xor 4,2,1 stays within each 8-group
            q += __shfl_xor_sync(0xFFFFFFFFu, q, off);
            d += __shfl_xor_sync(0xFFFFFFFFu, d, off);
        }
        if (lane == 0) {
            g_ssq[2 * bid] = q;
            g_ssd[2 * bid] = d;
        }
        if (lane == 8) {
            g_ssq[2 * bid + 1] = q;
            g_ssd[2 * bid + 1] = d;
        }
    }

    __syncthreads();
    cudaTriggerProgrammaticLaunchCompletion();
}

// ---------------------------------------------------------------------------
// Kernel 2: select + final (PDL secondary). 128 blocks x 512 threads.
// Each block: one (batch, 128-channel group). The 512-way rank count per
// channel is split across FOUR threads (32 float4 iters each), combined via
// SMEM. Block partial folds into ONE packed u64 atomicAdd (sum: low 57 bits,
// arrival count: top 7). The 128th arrival computes the exact integer total,
// writes the scalar, resets g_acc. Integer adds commute -> deterministic.
// ---------------------------------------------------------------------------
__global__ __launch_bounds__(512) void select_final_kernel(float* __restrict__ out)
{
    // PDL: wait until the upstream grid's memory (g_ssq/g_ssd) is visible.
    cudaGridDependencySynchronize();

    __shared__ float4 s_norm4[C_DIM / 4];   // all 512 norms of this batch
    __shared__ int    s_cnt[3 * 128];       // partial counts from quarters 1..3
    __shared__ float  s_p[4];

    const int b  = blockIdx.x >> 2;    // batch
    const int g  = blockIdx.x & 3;     // channel group (128 channels)
    const int t  = threadIdx.x;        // 0..511
    const int cl = t & 127;            // channel-within-group
    const int qt = t >> 7;             // which quarter of the 512 norms to scan
    const int warp = t >> 5;
    const int lane = t & 31;
    const int c = g * 128 + cl;        // this thread's channel

    // Hoist global loads: latency hides under the rank loop.
    const float my_ssd = (qt == 0) ? g_ssd[b * C_DIM + c] : 0.0f;
    if (t < C_DIM / 4)
        s_norm4[t] = reinterpret_cast<const float4*>(g_ssq + b * C_DIM)[t];
    __syncthreads();

    const float v = reinterpret_cast<const float*>(s_norm4)[c];

    // Each thread scans 32 float4 (128 norms): quarter qt -> j in [32qt, 32qt+32).
    int cnt = 0;
    const int j0 = qt * 32;
#pragma unroll 4
    for (int j = j0; j < j0 + 32; j++) {
        float4 n = s_norm4[j];         // broadcast, conflict-free
        cnt += (n.x > v) ? 1 : 0;
        cnt += (n.y > v) ? 1 : 0;
        cnt += (n.z > v) ? 1 : 0;
        cnt += (n.w > v) ? 1 : 0;
    }

    if (qt != 0) s_cnt[(qt - 1) * 128 + cl] = cnt;
    __syncthreads();

    float contrib = 0.0f;
    if (qt == 0) {
        const int total_cnt = cnt + s_cnt[cl] + s_cnt[128 + cl] + s_cnt[256 + cl];
        contrib = (total_cnt < KTOP) ? my_ssd : 0.0f;
    }

    // Only warps 0-3 (qt==0 threads) hold nonzero contribs; others skip.
    if (warp < 4) {
#pragma unroll
        for (int off = 16; off > 0; off >>= 1)
            contrib += __shfl_xor_sync(0xFFFFFFFFu, contrib, off);
        if (lane == 0) s_p[warp] = contrib;
    }
    __syncthreads();

    if (t == 0) {
        const float part = (s_p[0] + s_p[1]) + (s_p[2] + s_p[3]);
        // Fixed-point fold + arrival count, in ONE relaxed atomic.
        const unsigned long long mine =
            (unsigned long long)(part * FIXED_SCALE) + COUNT_INC;
        const unsigned long long prev = atomicAdd(&g_acc, mine);
        if ((prev >> 57) == (unsigned long long)(SEL_BLOCKS - 1)) {
            const unsigned long long tot = (prev & SUM_MASK) + (mine & SUM_MASK);
            out[0] = ((float)tot / FIXED_SCALE)
                   / ((float)HW * (float)(B_DIM * KTOP));
            g_acc = 0ULL;              // reset for next graph replay
        }
    }
}

extern "C" void kernel_launch(void* const* d_in, const int* in_sizes, int n_in,
                              void* d_out, int out_size)
{
    const float* inputs  = (const float*)d_in[0];
    const float* targets = (const float*)d_in[1];
    float* out = (float*)d_out;

    bc_reduce_kernel<<<NBC / 2, 512>>>(inputs, targets);

    // Dependent launch with programmatic stream serialization (PDL):
    // select_final_kernel's launch/prologue overlaps bc_reduce's tail.
    cudaLaunchConfig_t cfg = {};
    cfg.gridDim  = dim3(SEL_BLOCKS);
    cfg.blockDim = dim3(512);
    cfg.dynamicSmemBytes = 0;
    cfg.stream = 0;   // legacy default stream (same as <<<>>> above)
    cudaLaunchAttribute attrs[1];
    attrs[0].id = cudaLaunchAttributeProgrammaticStreamSerialization;
    attrs[0].val.programmaticStreamSerializationAllowed = 1;
    cfg.attrs = attrs;
    cfg.numAttrs = 1;
    cudaLaunchKernelEx(&cfg, select_final_kernel, out);
}

// round 14
// speedup vs baseline: 1.0088x; 1.0024x over previous
#include <cuda_runtime.h>
#include <cuda_bf16.h>

// Problem shape (fixed by reference setup_inputs)
#define B_DIM 32
#define C_DIM 512
#define HW    4096            // 64*64
#define KTOP  256             // 0.5 * C
#define NBC   (B_DIM * C_DIM) // 16384
#define SEL_BLOCKS 128        // 32 batches x 4 channel groups

// Fixed-point encoding for the single-atomic final reduction.
// Block partial <= ~1.3e6; x 2^18 ~= 3.4e11; x128 blocks ~= 4.4e13 << 2^57.
// Arrival count lives in bits [57,64).
#define FIXED_SCALE 262144.0f            // 2^18
#define COUNT_INC   (1ULL << 57)
#define SUM_MASK    (COUNT_INC - 1ULL)

// Scratch (no cudaMalloc allowed; zero-initialized at module load)
__device__ float g_ssq[NBC];            // per-(b,c) sum of targets^2 (ranking key)
__device__ float g_ssd[NBC];            // per-(b,c) sum of (in - tgt)^2
__device__ unsigned long long g_acc;    // packed {count:7, fixed sum:57}; self-reset

// ---------------------------------------------------------------------------
// Kernel 1: streaming reduce (FROZEN — ~98% of the path-independent LTS
// throughput cap; exit path stays pure per the R4/R6/R8 n=3 lesson).
// 512 threads per block, two (b,c) planes per block, 8x LDG.128 streaming.
// ---------------------------------------------------------------------------
__global__ __launch_bounds__(512, 4) void bc_reduce_kernel(
    const float* __restrict__ inp,
    const float* __restrict__ tgt)
{
    const int bid = blockIdx.x;                 // 0 .. NBC/2-1
    const int t   = threadIdx.x;                // 0 .. 511
    const int half = t >> 8;                    // which plane
    const int t256 = t & 255;

    const size_t plane = (size_t)(2 * bid + half);
    const float4* __restrict__ ip =
        reinterpret_cast<const float4*>(inp + plane * HW);
    const float4* __restrict__ tp =
        reinterpret_cast<const float4*>(tgt + plane * HW);

    float ssq = 0.0f;
    float ssd = 0.0f;

#pragma unroll
    for (int i = 0; i < 4; i++) {
        float4 a = __ldcs(ip + t256 + i * 256);
        float4 b = __ldcs(tp + t256 + i * 256);
        ssq = fmaf(b.x, b.x, ssq);
        ssq = fmaf(b.y, b.y, ssq);
        ssq = fmaf(b.z, b.z, ssq);
        ssq = fmaf(b.w, b.w, ssq);
        float dx = a.x - b.x;
        float dy = a.y - b.y;
        float dz = a.z - b.z;
        float dw = a.w - b.w;
        ssd = fmaf(dx, dx, ssd);
        ssd = fmaf(dy, dy, ssd);
        ssd = fmaf(dz, dz, ssd);
        ssd = fmaf(dw, dw, ssd);
    }

#pragma unroll
    for (int off = 16; off > 0; off >>= 1) {
        ssq += __shfl_xor_sync(0xFFFFFFFFu, ssq, off);
        ssd += __shfl_xor_sync(0xFFFFFFFFu, ssd, off);
    }

    __shared__ float s_ssq[16];
    __shared__ float s_ssd[16];
    const int warp = t >> 5;                    // 0..15 (0-7 plane0, 8-15 plane1)
    const int lane = t & 31;
    if (lane == 0) {
        s_ssq[warp] = ssq;
        s_ssd[warp] = ssd;
    }
    __syncthreads();

    if (warp == 0) {
        float q = (lane < 16) ? s_ssq[lane] : 0.0f;
        float d = (lane < 16) ? s_ssd[lane] : 0.0f;
#pragma unroll
        for (int off = 4; off > 0; off >>= 1) {   // xor 4,2,1 stays within each 8-group
            q += __shfl_xor_sync(0xFFFFFFFFu, q, off);
            d += __shfl_xor_sync(0xFFFFFFFFu, d, off);
        }
        if (lane == 0) {
            g_ssq[2 * bid] = q;
            g_ssd[2 * bid] = d;
        }
        if (lane == 8) {
            g_ssq[2 * bid + 1] = q;
            g_ssd[2 * bid + 1] = d;
        }
    }

    __syncthreads();
    cudaTriggerProgrammaticLaunchCompletion();
}

// ---------------------------------------------------------------------------
// Kernel 2: select + final (PDL secondary). 128 blocks x 1024 threads.
// Each block: one (batch, 128-channel group). The 512-way rank count per
// channel is split across EIGHT threads (16 float4 iters each), combined via
// SMEM. Block partial folds into ONE packed u64 atomicAdd (sum: low 57 bits,
// arrival count: top 7). The 128th arrival computes the exact integer total,
// writes the scalar, resets g_acc. Integer adds commute -> deterministic.
// ---------------------------------------------------------------------------
__global__ __launch_bounds__(1024) void select_final_kernel(float* __restrict__ out)
{
    // PDL: wait until the upstream grid's memory (g_ssq/g_ssd) is visible.
    cudaGridDependencySynchronize();

    __shared__ float4 s_norm4[C_DIM / 4];   // all 512 norms of this batch
    __shared__ int    s_cnt[7 * 128];       // partial counts from eighths 1..7
    __shared__ float  s_p[4];

    const int b  = blockIdx.x >> 2;    // batch
    const int g  = blockIdx.x & 3;     // channel group (128 channels)
    const int t  = threadIdx.x;        // 0..1023
    const int cl = t & 127;            // channel-within-group
    const int qt = t >> 7;             // which eighth of the 512 norms to scan
    const int warp = t >> 5;
    const int lane = t & 31;
    const int c = g * 128 + cl;        // this thread's channel

    // Hoist global loads: latency hides under the rank loop.
    const float my_ssd = (qt == 0) ? g_ssd[b * C_DIM + c] : 0.0f;
    if (t < C_DIM / 4)
        s_norm4[t] = reinterpret_cast<const float4*>(g_ssq + b * C_DIM)[t];
    __syncthreads();

    const float v = reinterpret_cast<const float*>(s_norm4)[c];

    // Each thread scans 16 float4 (64 norms): eighth qt -> j in [16qt, 16qt+16).
    int cnt = 0;
    const int j0 = qt * 16;
#pragma unroll
    for (int j = j0; j < j0 + 16; j++) {
        float4 n = s_norm4[j];         // broadcast, conflict-free
        cnt += (n.x > v) ? 1 : 0;
        cnt += (n.y > v) ? 1 : 0;
        cnt += (n.z > v) ? 1 : 0;
        cnt += (n.w > v) ? 1 : 0;
    }

    if (qt != 0) s_cnt[(qt - 1) * 128 + cl] = cnt;
    __syncthreads();

    float contrib = 0.0f;
    if (qt == 0) {
        int total_cnt = cnt;
#pragma unroll
        for (int q8 = 0; q8 < 7; q8++)
            total_cnt += s_cnt[q8 * 128 + cl];
        contrib = (total_cnt < KTOP) ? my_ssd : 0.0f;
    }

    // Only warps 0-3 (qt==0 threads) hold nonzero contribs; others skip.
    if (warp < 4) {
#pragma unroll
        for (int off = 16; off > 0; off >>= 1)
            contrib += __shfl_xor_sync(0xFFFFFFFFu, contrib, off);
        if (lane == 0) s_p[warp] = contrib;
    }
    __syncthreads();

    if (t == 0) {
        const float part = (s_p[0] + s_p[1]) + (s_p[2] + s_p[3]);
        // Fixed-point fold + arrival count, in ONE relaxed atomic.
        const unsigned long long mine =
            (unsigned long long)(part * FIXED_SCALE) + COUNT_INC;
        const unsigned long long prev = atomicAdd(&g_acc, mine);
        if ((prev >> 57) == (unsigned long long)(SEL_BLOCKS - 1)) {
            const unsigned long long tot = (prev & SUM_MASK) + (mine & SUM_MASK);
            out[0] = ((float)tot / FIXED_SCALE)
                   / ((float)HW * (float)(B_DIM * KTOP));
            g_acc = 0ULL;              // reset for next graph replay
        }
    }
}

extern "C" void kernel_launch(void* const* d_in, const int* in_sizes, int n_in,
                              void* d_out, int out_size)
{
    const float* inputs  = (const float*)d_in[0];
    const float* targets = (const float*)d_in[1];
    float* out = (float*)d_out;

    bc_reduce_kernel<<<NBC / 2, 512>>>(inputs, targets);

    // Dependent launch with programmatic stream serialization (PDL):
    // select_final_kernel's launch/prologue overlaps bc_reduce's tail.
    cudaLaunchConfig_t cfg = {};
    cfg.gridDim  = dim3(SEL_BLOCKS);
    cfg.blockDim = dim3(1024);
    cfg.dynamicSmemBytes = 0;
    cfg.stream = 0;   // legacy default stream (same as <<<>>> above)
    cudaLaunchAttribute attrs[1];
    attrs[0].id = cudaLaunchAttributeProgrammaticStreamSerialization;
    attrs[0].val.programmaticStreamSerializationAllowed = 1;
    cfg.attrs = attrs;
    cfg.numAttrs = 1;
    cudaLaunchKernelEx(&cfg, select_final_kernel, out);
}